// round 16
// baseline (speedup 1.0000x reference)
#include <cuda_runtime.h>
#include <cuda_bf16.h>
#include <cstdint>
#include <math.h>

#define Dm 512
#define Tm 2048
#define Bm 2
#define Hm 8
#define Mtot 4096          // B*T
#define KC 64              // K-chunk
#define NSTEP 8            // 512/64
#define STGB 65536         // stage bytes {Ahi,Alo,Whi,Wlo} x 16KB
#define NSTAGE 3

// ---------------- scratch (__device__ globals) ------------------------------
__device__ float g_Q[Bm*Hm*Tm*64];   // (B,H,T,hd)
__device__ float g_K[Bm*Hm*Tm*64];
__device__ float g_V[Bm*Hm*Tm*64];
__device__ __nv_bfloat16 g_xhi[Mtot*Dm], g_xlo[Mtot*Dm];
__device__ __nv_bfloat16 g_Whi[4*Dm*Dm], g_Wlo[4*Dm*Dm];
__device__ __nv_bfloat16 g_ahi[Mtot*Dm], g_alo[Mtot*Dm];   // attention out, bf16 split

// ---------------- helpers ---------------------------------------------------
__device__ __forceinline__ uint32_t s2u(const void* p) {
    uint32_t a;
    asm("{\n\t.reg .u64 t;\n\tcvta.to.shared.u64 t, %1;\n\tcvt.u32.u64 %0, t;\n\t}"
        : "=r"(a) : "l"(p));
    return a;
}
#define SWZ(o) ((o) ^ (((o) >> 3) & 0x70))

__device__ __forceinline__ void cpasync16(uint32_t dst, const void* src) {
    asm volatile("cp.async.cg.shared.global [%0], [%1], 16;" :: "r"(dst), "l"(src));
}
__device__ __forceinline__ void cp_commit() {
    asm volatile("cp.async.commit_group;");
}

__device__ __forceinline__ void ldsm4(uint32_t (&r)[4], uint32_t addr) {
    asm volatile("ldmatrix.sync.aligned.m8n8.x4.shared.b16 {%0,%1,%2,%3}, [%4];"
                 : "=r"(r[0]), "=r"(r[1]), "=r"(r[2]), "=r"(r[3]) : "r"(addr));
}

__device__ __forceinline__ void mma_bf16(float (&c)[4], const uint32_t (&a)[4],
                                         uint32_t b0, uint32_t b1) {
    asm volatile(
        "mma.sync.aligned.m16n8k16.row.col.f32.bf16.bf16.f32 "
        "{%0,%1,%2,%3}, {%4,%5,%6,%7}, {%8,%9}, {%0,%1,%2,%3};"
        : "+f"(c[0]), "+f"(c[1]), "+f"(c[2]), "+f"(c[3])
        : "r"(a[0]), "r"(a[1]), "r"(a[2]), "r"(a[3]), "r"(b0), "r"(b1));
}

// fp32x4 -> bf16 hi/lo packed pairs
__device__ __forceinline__ void split4(float4 v, uint2& hi, uint2& lo) {
    __nv_bfloat16 h0 = __float2bfloat16(v.x), h1 = __float2bfloat16(v.y);
    __nv_bfloat16 h2 = __float2bfloat16(v.z), h3 = __float2bfloat16(v.w);
    __nv_bfloat16 l0 = __float2bfloat16(v.x - __bfloat162float(h0));
    __nv_bfloat16 l1 = __float2bfloat16(v.y - __bfloat162float(h1));
    __nv_bfloat16 l2 = __float2bfloat16(v.z - __bfloat162float(h2));
    __nv_bfloat16 l3 = __float2bfloat16(v.w - __bfloat162float(h3));
    hi.x = (uint32_t)__bfloat16_as_ushort(h0) | ((uint32_t)__bfloat16_as_ushort(h1) << 16);
    hi.y = (uint32_t)__bfloat16_as_ushort(h2) | ((uint32_t)__bfloat16_as_ushort(h3) << 16);
    lo.x = (uint32_t)__bfloat16_as_ushort(l0) | ((uint32_t)__bfloat16_as_ushort(l1) << 16);
    lo.y = (uint32_t)__bfloat16_as_ushort(l2) | ((uint32_t)__bfloat16_as_ushort(l3) << 16);
}

// ---------------- conversion (single kernel: x + 4 weights) -----------------
__global__ void cvt_all_kernel(const float* __restrict__ x,
                               const float* __restrict__ Wq, const float* __restrict__ Wk,
                               const float* __restrict__ Wv, const float* __restrict__ Wo) {
    const int NX = Mtot * Dm;          // 2M
    const int DD = Dm * Dm;            // 256K
    int idx = (blockIdx.x * 256 + threadIdx.x) * 4;
    if (idx < NX) {
        float4 v = *(const float4*)(x + idx);
        uint2 hi, lo; split4(v, hi, lo);
        *(uint2*)(g_xhi + idx) = hi; *(uint2*)(g_xlo + idx) = lo;
    } else {
        int r = idx - NX;
        int z = r / DD, o = r - z * DD;
        const float* W = (z == 0) ? Wq : (z == 1) ? Wk : (z == 2) ? Wv : Wo;
        float4 v = *(const float4*)(W + o);
        uint2 hi, lo; split4(v, hi, lo);
        *(uint2*)(g_Whi + (size_t)z * DD + o) = hi;
        *(uint2*)(g_Wlo + (size_t)z * DD + o) = lo;
    }
}

// ---------------- GEMM core: C(128x128) = A @ W^T ---------------------------
// Coalesced cp.async 3-stage pipeline. 512 threads, 16 warps (2m x 8n), warp
// tile 64x16. Warps de-phased WITHIN each SMSP: kt0 = wid>>2 so the 4 warps
// sharing an SMSP (wid === s mod 4) start at 4 different k-sub-tiles, letting
// one warp's ldsm hide under its SMSP-mates' HMMA bursts.
// dyn smem: 3 stages x 64KB = {Ahi,Alo,Whi,Wlo} 128 rows x 128B (SW128).
__device__ __forceinline__ void gemm_core(
    const __nv_bfloat16* __restrict__ Ahi, const __nv_bfloat16* __restrict__ Alo,
    const __nv_bfloat16* __restrict__ Whi, const __nv_bfloat16* __restrict__ Wlo,
    float (&acc)[4][2][4], char* sm)
{
    const int tid = threadIdx.x;
    const int wid = tid >> 5, lane = tid & 31;
    const int wm = wid >> 3, wn = wid & 7;
    const int kt0 = wid >> 2;          // de-phase WITHIN SMSP (wid%4 = smsp id)
    const int m0 = blockIdx.y * 128, n0 = blockIdx.x * 128;
    const uint32_t sb = s2u(sm);

    // loader: 4 arrays x 128 threads; 8 lanes cover one 128B row (coalesced)
    const int sel  = tid >> 7;          // 0:Ahi 1:Alo 2:Whi 3:Wlo
    const int g    = tid & 127;
    const int crow = g >> 3;            // 0..15
    const int cseg = g & 7;             // 16B col segment
    const __nv_bfloat16* src;
    if (sel == 0)      src = Ahi + (size_t)(m0 + crow) * Dm + cseg * 8;
    else if (sel == 1) src = Alo + (size_t)(m0 + crow) * Dm + cseg * 8;
    else if (sel == 2) src = Whi + (size_t)(n0 + crow) * Dm + cseg * 8;
    else               src = Wlo + (size_t)(n0 + crow) * Dm + cseg * 8;

    uint32_t swo[8];
#pragma unroll
    for (int it = 0; it < 8; it++) {
        uint32_t o = (uint32_t)(it * 16 + crow) * 128 + cseg * 16;
        swo[it] = sb + sel * 16384 + SWZ(o);
    }

    // prologue: issue chunks 0 and 1
#pragma unroll
    for (int s = 0; s < 2; s++) {
#pragma unroll
        for (int it = 0; it < 8; it++)
            cpasync16(swo[it] + s * STGB, src + s * KC + (size_t)(it * 16) * Dm);
        cp_commit();
    }

    // fragment addressing
    const int arow = wm * 64 + (lane & 15);
    const int ak8  = lane >> 4;
    const int brow = wn * 16 + ((lane >> 4) << 3) + (lane & 7);
    const int bk8  = (lane >> 3) & 1;

#pragma unroll
    for (int c = 0; c < NSTEP; c++) {
        const int buf = c % NSTAGE;
        if (c == NSTEP - 1) asm volatile("cp.async.wait_group 0;");
        else                asm volatile("cp.async.wait_group 1;");
        __syncthreads();   // chunk c visible; all warps done reading buf (c-1)%3

        if (c + 2 < NSTEP) {
            const int bufn = (c + 2) % NSTAGE;
#pragma unroll
            for (int it = 0; it < 8; it++)
                cpasync16(swo[it] + bufn * STGB,
                          src + (c + 2) * KC + (size_t)(it * 16) * Dm);
            cp_commit();
        }

        const uint32_t tbu = sb + buf * STGB;
#pragma unroll
        for (int ktl = 0; ktl < 4; ktl++) {
            const int kt = (ktl + kt0) & 3;   // staggered within each SMSP
            uint32_t ah[4][4], al[4][4];
#pragma unroll
            for (int mi = 0; mi < 4; mi++) {
                uint32_t off = (uint32_t)(arow + mi * 16) * 128 + (kt * 16 + ak8 * 8) * 2;
                uint32_t sw = SWZ(off);
                ldsm4(ah[mi], tbu + sw);
                ldsm4(al[mi], tbu + 16384 + sw);
            }
            uint32_t bh[4], bl[4];
            {
                uint32_t off = (uint32_t)brow * 128 + (kt * 16 + bk8 * 8) * 2;
                uint32_t sw = SWZ(off);
                ldsm4(bh, tbu + 32768 + sw);
                ldsm4(bl, tbu + 49152 + sw);
            }
#pragma unroll
            for (int mi = 0; mi < 4; mi++) {
#pragma unroll
                for (int nj = 0; nj < 2; nj++) {
                    mma_bf16(acc[mi][nj], ah[mi], bh[nj * 2], bh[nj * 2 + 1]);
                    mma_bf16(acc[mi][nj], ah[mi], bl[nj * 2], bl[nj * 2 + 1]);
                    mma_bf16(acc[mi][nj], al[mi], bh[nj * 2], bh[nj * 2 + 1]);
                }
            }
        }
    }
}

// ---------------- QKV projection --------------------------------------------
__global__ void __launch_bounds__(512, 1) qkv_mma_kernel(
    const float* __restrict__ bq, const float* __restrict__ bk, const float* __restrict__ bv)
{
    extern __shared__ __align__(16) char sm[];
    const int z = blockIdx.z;
    const __nv_bfloat16* Wh = g_Whi + (size_t)z * Dm * Dm;
    const __nv_bfloat16* Wl = g_Wlo + (size_t)z * Dm * Dm;
    const float* bias = (z == 0) ? bq : (z == 1) ? bk : bv;
    float* out        = (z == 0) ? g_Q : (z == 1) ? g_K : g_V;

    float acc[4][2][4] = {};
    gemm_core(g_xhi, g_xlo, Wh, Wl, acc, sm);

    const int wid = threadIdx.x >> 5, lane = threadIdx.x & 31;
    const int wm = wid >> 3, wn = wid & 7;
    const int m0 = blockIdx.y * 128, n0 = blockIdx.x * 128;
    const int b = m0 >> 11, t0 = m0 & (Tm - 1);
#pragma unroll
    for (int mi = 0; mi < 4; mi++) {
#pragma unroll
        for (int nj = 0; nj < 2; nj++) {
            int rowl = wm * 64 + mi * 16 + (lane >> 2);
            int n = n0 + wn * 16 + nj * 8 + (lane & 3) * 2;
            int h = n >> 6, d = n & 63;
            float2 bb = *(const float2*)(bias + n);
            size_t rb = ((size_t)(b * Hm + h) * Tm) << 6;
            float2 v0 = { acc[mi][nj][0] + bb.x, acc[mi][nj][1] + bb.y };
            float2 v1 = { acc[mi][nj][2] + bb.x, acc[mi][nj][3] + bb.y };
            *(float2*)&out[rb + ((size_t)(t0 + rowl) << 6) + d]     = v0;
            *(float2*)&out[rb + ((size_t)(t0 + rowl + 8) << 6) + d] = v1;
        }
    }
}

// ---------------- output projection -----------------------------------------
__global__ void __launch_bounds__(512, 1) oproj_mma_kernel(
    const float* __restrict__ bo, float* __restrict__ out)
{
    extern __shared__ __align__(16) char sm2[];
    float acc[4][2][4] = {};
    gemm_core(g_ahi, g_alo, g_Whi + 3 * (size_t)Dm * Dm, g_Wlo + 3 * (size_t)Dm * Dm,
              acc, sm2);

    const int wid = threadIdx.x >> 5, lane = threadIdx.x & 31;
    const int wm = wid >> 3, wn = wid & 7;
    const int m0 = blockIdx.y * 128, n0 = blockIdx.x * 128;
#pragma unroll
    for (int mi = 0; mi < 4; mi++) {
#pragma unroll
        for (int nj = 0; nj < 2; nj++) {
            int rowl = wm * 64 + mi * 16 + (lane >> 2);
            int n = n0 + wn * 16 + nj * 8 + (lane & 3) * 2;
            float2 bb = *(const float2*)(bo + n);
            float2 v0 = { acc[mi][nj][0] + bb.x, acc[mi][nj][1] + bb.y };
            float2 v1 = { acc[mi][nj][2] + bb.x, acc[mi][nj][3] + bb.y };
            *(float2*)&out[(size_t)(m0 + rowl) * Dm + n]     = v0;
            *(float2*)&out[(size_t)(m0 + rowl + 8) * Dm + n] = v1;
        }
    }
}

// ---------------- local-window attention ------------------------------------
// CTA: 64 queries, 256 threads (8 warps, 8 q/warp), 2 queries interleaved/iter.
// dyn smem 64KB: sK [0,6144) 96x64, sV [6144,12288) 96x64, sQ [12288,16384) 64x64.
__global__ void __launch_bounds__(256, 3) attn_kernel()
{
    extern __shared__ float sf[];
    const int tid = threadIdx.x;
    const int bh = blockIdx.y;
    const int q0 = blockIdx.x * 64;
    const int b0 = q0 - 16;
    const size_t base = (size_t)bh * Tm;

    for (int idx = tid; idx < 96 * 16; idx += 256) {
        int r = idx >> 4, d4 = (idx & 15) * 4;
        int row = b0 + r;
        float4 kv = {0.f, 0.f, 0.f, 0.f}, vv = {0.f, 0.f, 0.f, 0.f};
        if (row >= 0 && row < Tm) {
            kv = *(const float4*)(g_K + ((base + row) << 6) + d4);
            vv = *(const float4*)(g_V + ((base + row) << 6) + d4);
        }
        *(float4*)&sf[r * 64 + d4]        = kv;
        *(float4*)&sf[6144 + r * 64 + d4] = vv;
    }
    for (int idx = tid; idx < 64 * 16; idx += 256) {
        int r = idx >> 4, d4 = (idx & 15) * 4;
        *(float4*)&sf[12288 + r * 64 + d4] =
            *(const float4*)(g_Q + ((base + q0 + r) << 6) + d4);
    }
    __syncthreads();

    const int wid = tid >> 5, lane = tid & 31;
    const int b = bh >> 3, h = bh & 7;
#pragma unroll
    for (int t = 0; t < 4; t++) {
        const int iqa = q0 + wid * 8 + 2 * t;
        const int iqb = iqa + 1;
        const int sa_ = max(0, iqa - 16), ea = min(Tm, iqa + 16);
        const int sb_ = max(0, iqb - 16), eb = min(Tm, iqb + 16);
        const int cnta = ea - sa_, r0a = sa_ - b0;
        const int cntb = eb - sb_, r0b = sb_ - b0;

        float pa0 = 0.f, pa1 = 0.f, pa2 = 0.f, pa3 = 0.f;
        float pb0 = 0.f, pb1 = 0.f, pb2 = 0.f, pb3 = 0.f;
        {
            const float4* kra = (const float4*)&sf[(r0a + lane) * 64];
            const float4* krb = (const float4*)&sf[(r0b + lane) * 64];
            const float4* qra = (const float4*)&sf[12288 + (iqa - q0) * 64];
            const float4* qrb = (const float4*)&sf[12288 + (iqb - q0) * 64];
#pragma unroll
            for (int cc = 0; cc < 16; cc += 4) {
#pragma unroll
                for (int u = 0; u < 4; u++) {
                    int ci = (cc + u + lane) & 15;
                    float4 qa = qra[ci], ka = kra[ci];
                    float4 qb = qrb[ci], kb = krb[ci];
                    float da = qa.x * ka.x + qa.y * ka.y + qa.z * ka.z + qa.w * ka.w;
                    float db = qb.x * kb.x + qb.y * kb.y + qb.z * kb.z + qb.w * kb.w;
                    if (u == 0) { pa0 += da; pb0 += db; }
                    else if (u == 1) { pa1 += da; pb1 += db; }
                    else if (u == 2) { pa2 += da; pb2 += db; }
                    else { pa3 += da; pb3 += db; }
                }
            }
        }
        float sca = (lane < cnta) ? ((pa0 + pa1) + (pa2 + pa3)) * 0.125f : -INFINITY;
        float scb = (lane < cntb) ? ((pb0 + pb1) + (pb2 + pb3)) * 0.125f : -INFINITY;

        float ma = sca, mb = scb;
#pragma unroll
        for (int off = 16; off; off >>= 1) {
            ma = fmaxf(ma, __shfl_xor_sync(0xffffffffu, ma, off));
            mb = fmaxf(mb, __shfl_xor_sync(0xffffffffu, mb, off));
        }
        float pa = __expf(sca - ma);
        float pb = __expf(scb - mb);
        float sua = pa, sub = pb;
#pragma unroll
        for (int off = 16; off; off >>= 1) {
            sua += __shfl_xor_sync(0xffffffffu, sua, off);
            sub += __shfl_xor_sync(0xffffffffu, sub, off);
        }
        const float inva = 1.0f / sua, invb = 1.0f / sub;

        float axa = 0.f, aya = 0.f, axb = 0.f, ayb = 0.f;
        const float2* vba = (const float2*)&sf[6144 + r0a * 64];
        const float2* vbb = (const float2*)&sf[6144 + r0b * 64];
#pragma unroll
        for (int j = 0; j < 32; j++) {
            float pja = __shfl_sync(0xffffffffu, pa, j);
            float pjb = __shfl_sync(0xffffffffu, pb, j);
            float2 va = vba[j * 32 + lane];
            float2 vb = vbb[j * 32 + lane];
            axa = fmaf(pja, va.x, axa); aya = fmaf(pja, va.y, aya);
            axb = fmaf(pjb, vb.x, axb); ayb = fmaf(pjb, vb.y, ayb);
        }
        float oxa = axa * inva, oya = aya * inva;
        float oxb = axb * invb, oyb = ayb * invb;

        size_t offa = (size_t)(b * Tm + iqa) * Dm + (h << 6) + 2 * lane;
        size_t offb = (size_t)(b * Tm + iqb) * Dm + (h << 6) + 2 * lane;
        __nv_bfloat16 hxa = __float2bfloat16(oxa), hya = __float2bfloat16(oya);
        __nv_bfloat16 lxa = __float2bfloat16(oxa - __bfloat162float(hxa));
        __nv_bfloat16 lya = __float2bfloat16(oya - __bfloat162float(hya));
        __nv_bfloat16 hxb = __float2bfloat16(oxb), hyb = __float2bfloat16(oyb);
        __nv_bfloat16 lxb = __float2bfloat16(oxb - __bfloat162float(hxb));
        __nv_bfloat16 lyb = __float2bfloat16(oyb - __bfloat162float(hyb));
        __nv_bfloat162 hva; hva.x = hxa; hva.y = hya;
        __nv_bfloat162 lva; lva.x = lxa; lva.y = lya;
        __nv_bfloat162 hvb; hvb.x = hxb; hvb.y = hyb;
        __nv_bfloat162 lvb; lvb.x = lxb; lvb.y = lyb;
        *(__nv_bfloat162*)(g_ahi + offa) = hva;
        *(__nv_bfloat162*)(g_alo + offa) = lva;
        *(__nv_bfloat162*)(g_ahi + offb) = hvb;
        *(__nv_bfloat162*)(g_alo + offb) = lvb;
    }
}

// ---------------- launch -----------------------------------------------------
extern "C" void kernel_launch(void* const* d_in, const int* in_sizes, int n_in,
                              void* d_out, int out_size)
{
    const float* x  = (const float*)d_in[0];
    const float* Wq = (const float*)d_in[1];
    const float* bq = (const float*)d_in[2];
    const float* Wk = (const float*)d_in[3];
    const float* bk = (const float*)d_in[4];
    const float* Wv = (const float*)d_in[5];
    const float* bv = (const float*)d_in[6];
    const float* Wo = (const float*)d_in[7];
    const float* bo = (const float*)d_in[8];
    float* out = (float*)d_out;

    cudaFuncSetAttribute(qkv_mma_kernel,   cudaFuncAttributeMaxDynamicSharedMemorySize, NSTAGE * STGB);
    cudaFuncSetAttribute(oproj_mma_kernel, cudaFuncAttributeMaxDynamicSharedMemorySize, NSTAGE * STGB);
    cudaFuncSetAttribute(attn_kernel,      cudaFuncAttributeMaxDynamicSharedMemorySize, 65536);

    // 3M elements total (x: 2M, weights: 4 x 256K), 4 per thread
    cvt_all_kernel<<<3072, 256>>>(x, Wq, Wk, Wv, Wo);

    qkv_mma_kernel<<<dim3(Dm / 128, Mtot / 128, 3), 512, NSTAGE * STGB>>>(bq, bk, bv);

    attn_kernel<<<dim3(Tm / 64, Bm * Hm), 256, 65536>>>();

    oproj_mma_kernel<<<dim3(Dm / 128, Mtot / 128), 512, NSTAGE * STGB>>>(bo, out);
}

// round 17
// speedup vs baseline: 1.4297x; 1.4297x over previous
#include <cuda_runtime.h>
#include <cuda_fp16.h>
#include <cstdint>
#include <math.h>

#define Dm 512
#define Tm 2048
#define Bm 2
#define Hm 8
#define Mtot 4096          // B*T
#define KC 64              // K-chunk
#define NSTEP 8            // 512/64
#define STGB 32768         // stage bytes {A 16KB, W 16KB}
#define NSTAGE 3

// ---------------- scratch (__device__ globals) ------------------------------
__device__ float g_Q[Bm*Hm*Tm*64];   // (B,H,T,hd)
__device__ float g_K[Bm*Hm*Tm*64];
__device__ float g_V[Bm*Hm*Tm*64];
__device__ __half g_xh[Mtot*Dm];
__device__ __half g_Wh[4*Dm*Dm];
__device__ __half g_ah[Mtot*Dm];     // attention out (fp16, feeds oproj)

// ---------------- helpers ---------------------------------------------------
__device__ __forceinline__ uint32_t s2u(const void* p) {
    uint32_t a;
    asm("{\n\t.reg .u64 t;\n\tcvta.to.shared.u64 t, %1;\n\tcvt.u32.u64 %0, t;\n\t}"
        : "=r"(a) : "l"(p));
    return a;
}
#define SWZ(o) ((o) ^ (((o) >> 3) & 0x70))

__device__ __forceinline__ void cpasync16(uint32_t dst, const void* src) {
    asm volatile("cp.async.cg.shared.global [%0], [%1], 16;" :: "r"(dst), "l"(src));
}
__device__ __forceinline__ void cp_commit() {
    asm volatile("cp.async.commit_group;");
}

__device__ __forceinline__ void ldsm4(uint32_t (&r)[4], uint32_t addr) {
    asm volatile("ldmatrix.sync.aligned.m8n8.x4.shared.b16 {%0,%1,%2,%3}, [%4];"
                 : "=r"(r[0]), "=r"(r[1]), "=r"(r[2]), "=r"(r[3]) : "r"(addr));
}

__device__ __forceinline__ void mma_f16(float (&c)[4], const uint32_t (&a)[4],
                                        uint32_t b0, uint32_t b1) {
    asm volatile(
        "mma.sync.aligned.m16n8k16.row.col.f32.f16.f16.f32 "
        "{%0,%1,%2,%3}, {%4,%5,%6,%7}, {%8,%9}, {%0,%1,%2,%3};"
        : "+f"(c[0]), "+f"(c[1]), "+f"(c[2]), "+f"(c[3])
        : "r"(a[0]), "r"(a[1]), "r"(a[2]), "r"(a[3]), "r"(b0), "r"(b1));
}

// fp32x4 -> fp16x4 packed
__device__ __forceinline__ uint2 cvt4(float4 v) {
    __half2 p0 = __floats2half2_rn(v.x, v.y);
    __half2 p1 = __floats2half2_rn(v.z, v.w);
    uint2 r;
    r.x = *(uint32_t*)&p0;
    r.y = *(uint32_t*)&p1;
    return r;
}

// ---------------- conversion (single kernel: x + 4 weights) -----------------
__global__ void cvt_all_kernel(const float* __restrict__ x,
                               const float* __restrict__ Wq, const float* __restrict__ Wk,
                               const float* __restrict__ Wv, const float* __restrict__ Wo) {
    const int NX = Mtot * Dm;          // 2M
    const int DD = Dm * Dm;            // 256K
    int idx = (blockIdx.x * 256 + threadIdx.x) * 4;
    if (idx < NX) {
        *(uint2*)(g_xh + idx) = cvt4(*(const float4*)(x + idx));
    } else {
        int r = idx - NX;
        int z = r / DD, o = r - z * DD;
        const float* W = (z == 0) ? Wq : (z == 1) ? Wk : (z == 2) ? Wv : Wo;
        *(uint2*)(g_Wh + (size_t)z * DD + o) = cvt4(*(const float4*)(W + o));
    }
}

// ---------------- GEMM core: C(128x128) = A @ W^T (fp16 single-term) --------
// Coalesced cp.async 3-stage pipeline. 512 threads, 16 warps (2m x 8n), warp
// tile 64x16. dyn smem: 3 stages x 32KB = {A, W} 128 rows x 128B (SW128).
__device__ __forceinline__ void gemm_core(
    const __half* __restrict__ A, const __half* __restrict__ W,
    float (&acc)[4][2][4], char* sm)
{
    const int tid = threadIdx.x;
    const int wid = tid >> 5, lane = tid & 31;
    const int wm = wid >> 3, wn = wid & 7;
    const int kt0 = wid >> 2;          // stagger within SMSP (harmless, keep)
    const int m0 = blockIdx.y * 128, n0 = blockIdx.x * 128;
    const uint32_t sb = s2u(sm);

    // loader: 2 arrays x 256 threads; 8 lanes cover one 128B row (coalesced)
    const int sel  = tid >> 8;          // 0:A 1:W
    const int g    = tid & 255;
    const int crow = g >> 3;            // 0..31
    const int cseg = g & 7;             // 16B col segment
    const __half* src = sel ? (W + (size_t)(n0 + crow) * Dm + cseg * 8)
                            : (A + (size_t)(m0 + crow) * Dm + cseg * 8);

    uint32_t swo[4];
#pragma unroll
    for (int it = 0; it < 4; it++) {
        uint32_t o = (uint32_t)(it * 32 + crow) * 128 + cseg * 16;
        swo[it] = sb + sel * 16384 + SWZ(o);
    }

    // prologue: issue chunks 0 and 1
#pragma unroll
    for (int s = 0; s < 2; s++) {
#pragma unroll
        for (int it = 0; it < 4; it++)
            cpasync16(swo[it] + s * STGB, src + s * KC + (size_t)(it * 32) * Dm);
        cp_commit();
    }

    // fragment addressing
    const int arow = wm * 64 + (lane & 15);
    const int ak8  = lane >> 4;
    const int brow = wn * 16 + ((lane >> 4) << 3) + (lane & 7);
    const int bk8  = (lane >> 3) & 1;

#pragma unroll
    for (int c = 0; c < NSTEP; c++) {
        const int buf = c % NSTAGE;
        if (c == NSTEP - 1) asm volatile("cp.async.wait_group 0;");
        else                asm volatile("cp.async.wait_group 1;");
        __syncthreads();   // chunk c visible; all warps done reading buf (c-1)%3

        if (c + 2 < NSTEP) {
            const int bufn = (c + 2) % NSTAGE;
#pragma unroll
            for (int it = 0; it < 4; it++)
                cpasync16(swo[it] + bufn * STGB,
                          src + (c + 2) * KC + (size_t)(it * 32) * Dm);
            cp_commit();
        }

        const uint32_t tbu = sb + buf * STGB;
#pragma unroll
        for (int ktl = 0; ktl < 4; ktl++) {
            const int kt = (ktl + kt0) & 3;
            uint32_t ah[4][4];
#pragma unroll
            for (int mi = 0; mi < 4; mi++) {
                uint32_t off = (uint32_t)(arow + mi * 16) * 128 + (kt * 16 + ak8 * 8) * 2;
                ldsm4(ah[mi], tbu + SWZ(off));
            }
            uint32_t bh[4];
            {
                uint32_t off = (uint32_t)brow * 128 + (kt * 16 + bk8 * 8) * 2;
                ldsm4(bh, tbu + 16384 + SWZ(off));
            }
#pragma unroll
            for (int mi = 0; mi < 4; mi++) {
#pragma unroll
                for (int nj = 0; nj < 2; nj++)
                    mma_f16(acc[mi][nj], ah[mi], bh[nj * 2], bh[nj * 2 + 1]);
            }
        }
    }
}

// ---------------- QKV projection --------------------------------------------
__global__ void __launch_bounds__(512, 1) qkv_mma_kernel(
    const float* __restrict__ bq, const float* __restrict__ bk, const float* __restrict__ bv)
{
    extern __shared__ __align__(16) char sm[];
    const int z = blockIdx.z;
    const __half* Wh = g_Wh + (size_t)z * Dm * Dm;
    const float* bias = (z == 0) ? bq : (z == 1) ? bk : bv;
    float* out        = (z == 0) ? g_Q : (z == 1) ? g_K : g_V;

    float acc[4][2][4] = {};
    gemm_core(g_xh, Wh, acc, sm);

    const int wid = threadIdx.x >> 5, lane = threadIdx.x & 31;
    const int wm = wid >> 3, wn = wid & 7;
    const int m0 = blockIdx.y * 128, n0 = blockIdx.x * 128;
    const int b = m0 >> 11, t0 = m0 & (Tm - 1);
#pragma unroll
    for (int mi = 0; mi < 4; mi++) {
#pragma unroll
        for (int nj = 0; nj < 2; nj++) {
            int rowl = wm * 64 + mi * 16 + (lane >> 2);
            int n = n0 + wn * 16 + nj * 8 + (lane & 3) * 2;
            int h = n >> 6, d = n & 63;
            float2 bb = *(const float2*)(bias + n);
            size_t rb = ((size_t)(b * Hm + h) * Tm) << 6;
            float2 v0 = { acc[mi][nj][0] + bb.x, acc[mi][nj][1] + bb.y };
            float2 v1 = { acc[mi][nj][2] + bb.x, acc[mi][nj][3] + bb.y };
            *(float2*)&out[rb + ((size_t)(t0 + rowl) << 6) + d]     = v0;
            *(float2*)&out[rb + ((size_t)(t0 + rowl + 8) << 6) + d] = v1;
        }
    }
}

// ---------------- output projection -----------------------------------------
__global__ void __launch_bounds__(512, 1) oproj_mma_kernel(
    const float* __restrict__ bo, float* __restrict__ out)
{
    extern __shared__ __align__(16) char sm2[];
    float acc[4][2][4] = {};
    gemm_core(g_ah, g_Wh + 3 * (size_t)Dm * Dm, acc, sm2);

    const int wid = threadIdx.x >> 5, lane = threadIdx.x & 31;
    const int wm = wid >> 3, wn = wid & 7;
    const int m0 = blockIdx.y * 128, n0 = blockIdx.x * 128;
#pragma unroll
    for (int mi = 0; mi < 4; mi++) {
#pragma unroll
        for (int nj = 0; nj < 2; nj++) {
            int rowl = wm * 64 + mi * 16 + (lane >> 2);
            int n = n0 + wn * 16 + nj * 8 + (lane & 3) * 2;
            float2 bb = *(const float2*)(bo + n);
            float2 v0 = { acc[mi][nj][0] + bb.x, acc[mi][nj][1] + bb.y };
            float2 v1 = { acc[mi][nj][2] + bb.x, acc[mi][nj][3] + bb.y };
            *(float2*)&out[(size_t)(m0 + rowl) * Dm + n]     = v0;
            *(float2*)&out[(size_t)(m0 + rowl + 8) * Dm + n] = v1;
        }
    }
}

// ---------------- local-window attention ------------------------------------
// CTA: 64 queries, 256 threads (8 warps, 8 q/warp), 2 queries interleaved/iter.
// dyn smem 64KB: sK [0,6144) 96x64, sV [6144,12288) 96x64, sQ [12288,16384) 64x64.
__global__ void __launch_bounds__(256, 3) attn_kernel()
{
    extern __shared__ float sf[];
    const int tid = threadIdx.x;
    const int bh = blockIdx.y;
    const int q0 = blockIdx.x * 64;
    const int b0 = q0 - 16;
    const size_t base = (size_t)bh * Tm;

    for (int idx = tid; idx < 96 * 16; idx += 256) {
        int r = idx >> 4, d4 = (idx & 15) * 4;
        int row = b0 + r;
        float4 kv = {0.f, 0.f, 0.f, 0.f}, vv = {0.f, 0.f, 0.f, 0.f};
        if (row >= 0 && row < Tm) {
            kv = *(const float4*)(g_K + ((base + row) << 6) + d4);
            vv = *(const float4*)(g_V + ((base + row) << 6) + d4);
        }
        *(float4*)&sf[r * 64 + d4]        = kv;
        *(float4*)&sf[6144 + r * 64 + d4] = vv;
    }
    for (int idx = tid; idx < 64 * 16; idx += 256) {
        int r = idx >> 4, d4 = (idx & 15) * 4;
        *(float4*)&sf[12288 + r * 64 + d4] =
            *(const float4*)(g_Q + ((base + q0 + r) << 6) + d4);
    }
    __syncthreads();

    const int wid = tid >> 5, lane = tid & 31;
    const int b = bh >> 3, h = bh & 7;
#pragma unroll
    for (int t = 0; t < 4; t++) {
        const int iqa = q0 + wid * 8 + 2 * t;
        const int iqb = iqa + 1;
        const int sa_ = max(0, iqa - 16), ea = min(Tm, iqa + 16);
        const int sb_ = max(0, iqb - 16), eb = min(Tm, iqb + 16);
        const int cnta = ea - sa_, r0a = sa_ - b0;
        const int cntb = eb - sb_, r0b = sb_ - b0;

        float pa0 = 0.f, pa1 = 0.f, pa2 = 0.f, pa3 = 0.f;
        float pb0 = 0.f, pb1 = 0.f, pb2 = 0.f, pb3 = 0.f;
        {
            const float4* kra = (const float4*)&sf[(r0a + lane) * 64];
            const float4* krb = (const float4*)&sf[(r0b + lane) * 64];
            const float4* qra = (const float4*)&sf[12288 + (iqa - q0) * 64];
            const float4* qrb = (const float4*)&sf[12288 + (iqb - q0) * 64];
#pragma unroll
            for (int cc = 0; cc < 16; cc += 4) {
#pragma unroll
                for (int u = 0; u < 4; u++) {
                    int ci = (cc + u + lane) & 15;
                    float4 qa = qra[ci], ka = kra[ci];
                    float4 qb = qrb[ci], kb = krb[ci];
                    float da = qa.x * ka.x + qa.y * ka.y + qa.z * ka.z + qa.w * ka.w;
                    float db = qb.x * kb.x + qb.y * kb.y + qb.z * kb.z + qb.w * kb.w;
                    if (u == 0) { pa0 += da; pb0 += db; }
                    else if (u == 1) { pa1 += da; pb1 += db; }
                    else if (u == 2) { pa2 += da; pb2 += db; }
                    else { pa3 += da; pb3 += db; }
                }
            }
        }
        float sca = (lane < cnta) ? ((pa0 + pa1) + (pa2 + pa3)) * 0.125f : -INFINITY;
        float scb = (lane < cntb) ? ((pb0 + pb1) + (pb2 + pb3)) * 0.125f : -INFINITY;

        float ma = sca, mb = scb;
#pragma unroll
        for (int off = 16; off; off >>= 1) {
            ma = fmaxf(ma, __shfl_xor_sync(0xffffffffu, ma, off));
            mb = fmaxf(mb, __shfl_xor_sync(0xffffffffu, mb, off));
        }
        float pa = __expf(sca - ma);
        float pb = __expf(scb - mb);
        float sua = pa, sub = pb;
#pragma unroll
        for (int off = 16; off; off >>= 1) {
            sua += __shfl_xor_sync(0xffffffffu, sua, off);
            sub += __shfl_xor_sync(0xffffffffu, sub, off);
        }
        const float inva = 1.0f / sua, invb = 1.0f / sub;

        float axa = 0.f, aya = 0.f, axb = 0.f, ayb = 0.f;
        const float2* vba = (const float2*)&sf[6144 + r0a * 64];
        const float2* vbb = (const float2*)&sf[6144 + r0b * 64];
#pragma unroll
        for (int j = 0; j < 32; j++) {
            float pja = __shfl_sync(0xffffffffu, pa, j);
            float pjb = __shfl_sync(0xffffffffu, pb, j);
            float2 va = vba[j * 32 + lane];
            float2 vb = vbb[j * 32 + lane];
            axa = fmaf(pja, va.x, axa); aya = fmaf(pja, va.y, aya);
            axb = fmaf(pjb, vb.x, axb); ayb = fmaf(pjb, vb.y, ayb);
        }
        float oxa = axa * inva, oya = aya * inva;
        float oxb = axb * invb, oyb = ayb * invb;

        // write fp16 (consumed by oproj GEMM)
        size_t offa = (size_t)(b * Tm + iqa) * Dm + (h << 6) + 2 * lane;
        size_t offb = (size_t)(b * Tm + iqb) * Dm + (h << 6) + 2 * lane;
        __half2 hva = __floats2half2_rn(oxa, oya);
        __half2 hvb = __floats2half2_rn(oxb, oyb);
        *(__half2*)(g_ah + offa) = hva;
        *(__half2*)(g_ah + offb) = hvb;
    }
}

// ---------------- launch -----------------------------------------------------
extern "C" void kernel_launch(void* const* d_in, const int* in_sizes, int n_in,
                              void* d_out, int out_size)
{
    const float* x  = (const float*)d_in[0];
    const float* Wq = (const float*)d_in[1];
    const float* bq = (const float*)d_in[2];
    const float* Wk = (const float*)d_in[3];
    const float* bk = (const float*)d_in[4];
    const float* Wv = (const float*)d_in[5];
    const float* bv = (const float*)d_in[6];
    const float* Wo = (const float*)d_in[7];
    const float* bo = (const float*)d_in[8];
    float* out = (float*)d_out;

    cudaFuncSetAttribute(qkv_mma_kernel,   cudaFuncAttributeMaxDynamicSharedMemorySize, NSTAGE * STGB);
    cudaFuncSetAttribute(oproj_mma_kernel, cudaFuncAttributeMaxDynamicSharedMemorySize, NSTAGE * STGB);
    cudaFuncSetAttribute(attn_kernel,      cudaFuncAttributeMaxDynamicSharedMemorySize, 65536);

    // 3M elements total (x: 2M, weights: 4 x 256K), 4 per thread
    cvt_all_kernel<<<3072, 256>>>(x, Wq, Wk, Wv, Wo);

    qkv_mma_kernel<<<dim3(Dm / 128, Mtot / 128, 3), 512, NSTAGE * STGB>>>(bq, bk, bv);

    attn_kernel<<<dim3(Tm / 64, Bm * Hm), 256, 65536>>>();

    oproj_mma_kernel<<<dim3(Dm / 128, Mtot / 128), 512, NSTAGE * STGB>>>(bo, out);
}